// round 1
// baseline (speedup 1.0000x reference)
#include <cuda_runtime.h>

#define NTOK 65536
#define DDIM 2048
#define KEXP 64
#define BM   128
#define DT   32
#define NT   (DDIM / DT)     // 64 tiles
#define XS_STRIDE 33         // 32 + 1 pad (scalar broadcast reads)
#define WS_STRIDE 68         // 64 + 4 pad (keeps 16B alignment for LDS.128)
#define LS_STRIDE 68

__global__ __launch_bounds__(256, 3)
void top2gate_kernel(const float* __restrict__ x,
                     const float* __restrict__ W,
                     const float* __restrict__ b,
                     float* __restrict__ out) {
    // GEMM phase: xs double buffer [2][128][33], ws double buffer [2][32][68]
    // Epilogue reuses the same storage as ls[128][68].
    __shared__ float smem[2*BM*XS_STRIDE + 2*DT*WS_STRIDE];  // 12800 floats = 50 KB
    __shared__ int   s_i1[BM];
    __shared__ int   s_i2[BM];
    __shared__ float s_q1[BM];
    __shared__ float s_q2[BM];

    float* xsb[2] = { smem, smem + BM*XS_STRIDE };
    float* wsb[2] = { smem + 2*BM*XS_STRIDE, smem + 2*BM*XS_STRIDE + DT*WS_STRIDE };

    const int tid = threadIdx.x;
    const int tx  = tid & 15;        // 16 col-groups
    const int ty  = tid >> 4;        // 16 row-groups
    const int r0  = ty * 8;          // 8 rows per thread
    const int c0  = tx * 4;          // 4 cols per thread
    const int row0 = blockIdx.x * BM;

    const int lkk = tid & 31;        // load: position within D-tile (coalesced)
    const int lr  = tid >> 5;        // load: row/col base 0..7

    const float* xbase = x + (size_t)row0 * DDIM + lkk;
    const float* wbase = W + lkk;

    float acc[8][4];
    #pragma unroll
    for (int r = 0; r < 8; r++)
        #pragma unroll
        for (int c = 0; c < 4; c++) acc[r][c] = 0.f;

    float xg[16], wg[8];

    // ---- prologue: stage tile 0 ----
    #pragma unroll
    for (int p = 0; p < 16; p++) xg[p] = xbase[(size_t)(lr + 8*p) * DDIM];
    #pragma unroll
    for (int p = 0; p < 8;  p++) wg[p] = wbase[(size_t)(lr + 8*p) * DDIM];
    #pragma unroll
    for (int p = 0; p < 16; p++) xsb[0][(lr + 8*p)*XS_STRIDE + lkk] = xg[p];
    #pragma unroll
    for (int p = 0; p < 8;  p++) wsb[0][lkk*WS_STRIDE + lr + 8*p]   = wg[p];
    __syncthreads();

    // ---- main D loop, double buffered ----
    for (int t = 0; t < NT; t++) {
        const int cur = t & 1;
        if (t + 1 < NT) {
            const float* xb = xbase + (t + 1) * DT;
            const float* wb = wbase + (t + 1) * DT;
            #pragma unroll
            for (int p = 0; p < 16; p++) xg[p] = xb[(size_t)(lr + 8*p) * DDIM];
            #pragma unroll
            for (int p = 0; p < 8;  p++) wg[p] = wb[(size_t)(lr + 8*p) * DDIM];
        }
        const float* xsC = xsb[cur];
        const float* wsC = wsb[cur];
        #pragma unroll
        for (int kk = 0; kk < DT; kk++) {
            float4 wv = *(const float4*)&wsC[kk*WS_STRIDE + c0];
            float xr[8];
            #pragma unroll
            for (int r = 0; r < 8; r++) xr[r] = xsC[(r0 + r)*XS_STRIDE + kk];
            #pragma unroll
            for (int r = 0; r < 8; r++) {
                acc[r][0] = fmaf(xr[r], wv.x, acc[r][0]);
                acc[r][1] = fmaf(xr[r], wv.y, acc[r][1]);
                acc[r][2] = fmaf(xr[r], wv.z, acc[r][2]);
                acc[r][3] = fmaf(xr[r], wv.w, acc[r][3]);
            }
        }
        if (t + 1 < NT) {
            const int nxt = cur ^ 1;
            #pragma unroll
            for (int p = 0; p < 16; p++) xsb[nxt][(lr + 8*p)*XS_STRIDE + lkk] = xg[p];
            #pragma unroll
            for (int p = 0; p < 8;  p++) wsb[nxt][lkk*WS_STRIDE + lr + 8*p]   = wg[p];
        }
        __syncthreads();
    }

    // ---- epilogue ----
    // add bias, park logits in smem (reuses GEMM buffers; loop ended with sync)
    float bv0 = b[c0 + 0], bv1 = b[c0 + 1], bv2 = b[c0 + 2], bv3 = b[c0 + 3];
    float* ls = smem;  // [BM][LS_STRIDE]
    #pragma unroll
    for (int r = 0; r < 8; r++) {
        float4 v;
        v.x = acc[r][0] + bv0;
        v.y = acc[r][1] + bv1;
        v.z = acc[r][2] + bv2;
        v.w = acc[r][3] + bv3;
        *(float4*)&ls[(r0 + r)*LS_STRIDE + c0] = v;
    }
    __syncthreads();

    float* out_p = out;                               // top2_probs [N][K]
    float* out_e = out + (size_t)NTOK * KEXP;         // entropy    [N]
    float* out_l = out_e + NTOK;                      // logits     [N][K]

    if (tid < BM) {
        const int row = tid;
        const float* lrow = &ls[row * LS_STRIDE];
        // top-2 scan; strict '>' matches jax top_k tie-break (lower index wins)
        float m1 = -1e30f, m2 = -1e30f;
        int i1 = 0, i2 = 0;
        #pragma unroll
        for (int c = 0; c < KEXP; c++) {
            float v = lrow[c];
            if (v > m1)      { m2 = m1; i2 = i1; m1 = v; i1 = c; }
            else if (v > m2) { m2 = v;  i2 = c; }
        }
        float Z = 0.f;
        #pragma unroll
        for (int c = 0; c < KEXP; c++) Z += expf(lrow[c] - m1);
        float p1 = 1.0f / Z;                 // exp(m1-m1)=1
        float p2 = expf(m2 - m1) / Z;
        float denom = p1 + p2 + 1e-9f;
        float q1 = p1 / denom;
        float q2 = p2 / denom;
        float ent = -(q1 * logf(fmaxf(q1, 1e-12f)) +
                      q2 * logf(fmaxf(q2, 1e-12f)));
        s_i1[row] = i1; s_i2[row] = i2; s_q1[row] = q1; s_q2[row] = q2;
        out_e[row0 + row] = ent;
    }
    __syncthreads();

    // coalesced sweep: write top2_probs and logits (128 rows x 16 float4)
    #pragma unroll
    for (int i = 0; i < 8; i++) {
        int idx = tid + 256 * i;       // 0..2047
        int row = idx >> 4;
        int col = (idx & 15) * 4;
        int i1 = s_i1[row], i2 = s_i2[row];
        float q1 = s_q1[row], q2 = s_q2[row];
        float4 pv;
        pv.x = (col + 0 == i1) ? q1 : ((col + 0 == i2) ? q2 : 0.f);
        pv.y = (col + 1 == i1) ? q1 : ((col + 1 == i2) ? q2 : 0.f);
        pv.z = (col + 2 == i1) ? q1 : ((col + 2 == i2) ? q2 : 0.f);
        pv.w = (col + 3 == i1) ? q1 : ((col + 3 == i2) ? q2 : 0.f);
        float4 lv = *(float4*)&ls[row * LS_STRIDE + col];
        size_t g = (size_t)(row0 + row) * KEXP + col;
        *(float4*)&out_p[g] = pv;
        *(float4*)&out_l[g] = lv;
    }
}

extern "C" void kernel_launch(void* const* d_in, const int* in_sizes, int n_in,
                              void* d_out, int out_size) {
    const float* x = (const float*)d_in[0];
    const float* W = (const float*)d_in[1];
    const float* b = (const float*)d_in[2];
    top2gate_kernel<<<NTOK / BM, 256>>>(x, W, b, (float*)d_out);
}

// round 4
// speedup vs baseline: 1.4203x; 1.4203x over previous
#include <cuda_runtime.h>
#include <cstdint>

#define NTOK 65536
#define DDIM 2048
#define KEXP 64
#define BM   128
#define KC   32
#define NCHUNK (DDIM / KC)          // 64
#define ASTRIDE 36                  // fp32 words per A row (32 + 4 pad) -> conflict-free
#define ABUF_BYTES (BM * ASTRIDE * 4)        // 18432
#define SB_OFF     (2 * ABUF_BYTES)          // 36864
#define BBUF_BYTES (2 * 4 * 8 * 64 * 4)      // [plane][k8][n8][64 words] = 16384
#define SMEM_TOTAL (SB_OFF + 2 * BBUF_BYTES) // 69632
#define LS_STRIDE 68
#define TIE_TAU 2e-3f
#define MAXFIX 8192

// W pre-split into tf32 hi/lo planes, FRAGMENT-MAJOR:
// word index = ((p*256 + kb)*8 + nb)*64 + lane*2 + reg
//   value = plane_p of W[n][k], n = nb*8 + (lane>>2), k = kb*8 + (lane&3) + 4*reg
__device__ uint32_t g_Wf[2 * 256 * 8 * 64];
__device__ int g_cnt;
__device__ int g_rows[MAXFIX];

__global__ void wprep_kernel(const float* __restrict__ W) {
    int i = blockIdx.x * 256 + threadIdx.x;          // 0 .. 262143
    if (i == 0) g_cnt = 0;                           // reset flag list every launch
    int reg  = i & 1;
    int lane = (i >> 1) & 31;
    int nb   = (i >> 6) & 7;
    int kb   = (i >> 9) & 255;
    int p    = i >> 17;
    int n = nb * 8 + (lane >> 2);
    int k = kb * 8 + (lane & 3) + reg * 4;
    float v = W[n * DDIM + k];
    uint32_t hv = __float_as_uint(v) & 0xFFFFE000u;  // exact tf32 (trunc 13 bits)
    if (p == 0) {
        g_Wf[i] = hv;
    } else {
        float lo = v - __uint_as_float(hv);          // exact residual
        uint32_t lr;
        asm("cvt.rna.tf32.f32 %0, %1;" : "=r"(lr) : "f"(lo));
        g_Wf[i] = lr;
    }
}

#define CP16(dst_u32, src_ptr) \
    asm volatile("cp.async.cg.shared.global [%0], [%1], 16;" :: "r"(dst_u32), "l"(src_ptr))
#define CP_COMMIT() asm volatile("cp.async.commit_group;" ::: "memory")

#define MMA_TF32(c, a, b2) \
    asm volatile("mma.sync.aligned.m16n8k8.row.col.f32.tf32.tf32.f32 " \
                 "{%0,%1,%2,%3}, {%4,%5,%6,%7}, {%8,%9}, {%0,%1,%2,%3};" \
                 : "+f"((c)[0]), "+f"((c)[1]), "+f"((c)[2]), "+f"((c)[3]) \
                 : "r"((a)[0]), "r"((a)[1]), "r"((a)[2]), "r"((a)[3]), \
                   "r"((b2)[0]), "r"((b2)[1]))

__global__ __launch_bounds__(256, 2)
void top2gate_tc(const float* __restrict__ x,
                 const float* __restrict__ b,
                 float* __restrict__ out) {
    extern __shared__ char smem[];
    uint32_t sb;
    asm("{ .reg .u64 t; cvta.to.shared.u64 t, %1; cvt.u32.u64 %0, t; }"
        : "=r"(sb) : "l"((const void*)smem));

    __shared__ float s_bias[KEXP];
    __shared__ int   s_i1[BM], s_i2[BM];
    __shared__ float s_q1[BM], s_q2[BM];

    const int tid  = threadIdx.x;
    const int lane = tid & 31;
    const int wid  = tid >> 5;
    const int g    = lane >> 2;       // groupID 0..7
    const int tg   = lane & 3;        // tid-in-group
    const int m0   = (wid >> 1) * 32; // warp M-tile base
    const int nbb  = (wid & 1) * 4;   // warp n8-block base
    const int row0 = blockIdx.x * BM;

    if (tid < KEXP) s_bias[tid] = b[tid];

    float acc[2][4][4];
    #pragma unroll
    for (int i = 0; i < 2; i++)
        #pragma unroll
        for (int j = 0; j < 4; j++)
            #pragma unroll
            for (int c = 0; c < 4; c++) acc[i][j][c] = 0.f;

    // ---- async chunk copy: A (raw fp32 x rows) + B (pre-split fragment words) ----
    auto issue_chunk = [&](int t) {
        const int buf = t & 1;
        const float* xs = x + (size_t)row0 * DDIM + t * KC;
        uint32_t da = sb + buf * ABUF_BYTES;
        #pragma unroll
        for (int q = 0; q < 4; q++) {
            int idx = tid + 256 * q;          // 0..1023
            int r   = idx >> 3;               // row 0..127
            int seg = idx & 7;                // 16B segment
            CP16(da + (uint32_t)(r * ASTRIDE + seg * 4) * 4,
                 xs + (size_t)r * DDIM + seg * 4);
        }
        uint32_t db = sb + SB_OFF + buf * BBUF_BYTES;
        #pragma unroll
        for (int q = 0; q < 4; q++) {
            int idx = tid + 256 * q;          // 0..1023
            int wo  = idx * 4;                // word offset in buffer, 0..4095
            int pl  = wo >> 11;
            int rem = wo & 2047;
            CP16(db + (uint32_t)wo * 4,
                 (const void*)(g_Wf + pl * 131072 + t * 2048 + rem));
        }
        CP_COMMIT();
    };

    issue_chunk(0);

    for (int t = 0; t < NCHUNK; t++) {
        if (t + 1 < NCHUNK) {
            issue_chunk(t + 1);
            asm volatile("cp.async.wait_group 1;" ::: "memory");
        } else {
            asm volatile("cp.async.wait_group 0;" ::: "memory");
        }
        __syncthreads();

        const int buf = t & 1;
        const float* A = (const float*)(smem + buf * ABUF_BYTES);
        const uint32_t dbB = sb + SB_OFF + buf * BBUF_BYTES;

        #pragma unroll
        for (int kq = 0; kq < 4; kq++) {
            // A fragments: raw fp32 -> hi (mask) + lo (sub + tf32 round)
            float ar[2][4];
            const int c0 = kq * 8 + tg;
            #pragma unroll
            for (int i = 0; i < 2; i++) {
                const int rb = m0 + 16 * i + g;
                ar[i][0] = A[rb * ASTRIDE + c0];
                ar[i][1] = A[(rb + 8) * ASTRIDE + c0];
                ar[i][2] = A[rb * ASTRIDE + c0 + 4];
                ar[i][3] = A[(rb + 8) * ASTRIDE + c0 + 4];
            }
            uint32_t ah[2][4], al[2][4];
            #pragma unroll
            for (int i = 0; i < 2; i++)
                #pragma unroll
                for (int j = 0; j < 4; j++) {
                    ah[i][j] = __float_as_uint(ar[i][j]) & 0xFFFFE000u;
                    float lo = ar[i][j] - __uint_as_float(ah[i][j]);
                    asm("cvt.rna.tf32.f32 %0, %1;" : "=r"(al[i][j]) : "f"(lo));
                }
            // B fragments (LDS.64 each)
            uint32_t bh[4][2], bl[4][2];
            #pragma unroll
            for (int jn = 0; jn < 4; jn++) {
                uint32_t addrh = dbB + (uint32_t)(((0 * 4 + kq) * 8 + nbb + jn) * 256 + lane * 8);
                uint32_t addrl = dbB + (uint32_t)(((1 * 4 + kq) * 8 + nbb + jn) * 256 + lane * 8);
                asm volatile("ld.shared.v2.b32 {%0,%1}, [%2];"
                             : "=r"(bh[jn][0]), "=r"(bh[jn][1]) : "r"(addrh));
                asm volatile("ld.shared.v2.b32 {%0,%1}, [%2];"
                             : "=r"(bl[jn][0]), "=r"(bl[jn][1]) : "r"(addrl));
            }
            // 3 split-products, all into one fp32 accumulator
            #pragma unroll
            for (int i = 0; i < 2; i++)
                #pragma unroll
                for (int jn = 0; jn < 4; jn++) {
                    MMA_TF32(acc[i][jn], ah[i], bh[jn]);
                    MMA_TF32(acc[i][jn], ah[i], bl[jn]);
                    MMA_TF32(acc[i][jn], al[i], bh[jn]);
                }
        }
        __syncthreads();
    }

    // ---- epilogue: park logits (no bias yet) in smem, reusing A buffers ----
    float* ls = (float*)smem;   // [BM][LS_STRIDE]
    #pragma unroll
    for (int i = 0; i < 2; i++)
        #pragma unroll
        for (int jn = 0; jn < 4; jn++) {
            int r = m0 + 16 * i + g;
            int c = nbb * 8 + jn * 8 + 2 * tg;
            *(float2*)&ls[r * LS_STRIDE + c]       = make_float2(acc[i][jn][0], acc[i][jn][1]);
            *(float2*)&ls[(r + 8) * LS_STRIDE + c] = make_float2(acc[i][jn][2], acc[i][jn][3]);
        }
    __syncthreads();

    float* out_p = out;
    float* out_e = out + (size_t)NTOK * KEXP;
    float* out_l = out_e + NTOK;

    if (tid < BM) {
        const int row = tid;
        const float* lrow = &ls[row * LS_STRIDE];
        float m1 = -1e30f, m2 = -1e30f, m3 = -1e30f;
        int i1 = 0, i2 = 0;
        #pragma unroll
        for (int c = 0; c < KEXP; c++) {
            float v = lrow[c] + s_bias[c];
            if (v > m1)      { m3 = m2; m2 = m1; i2 = i1; m1 = v; i1 = c; }
            else if (v > m2) { m3 = m2; m2 = v;  i2 = c; }
            else if (v > m3) { m3 = v; }
        }
        // near-tie at the top-2/top-3 boundary -> flag for exact fp32 repair
        if (m2 - m3 < TIE_TAU) {
            int slot = atomicAdd(&g_cnt, 1);
            if (slot < MAXFIX) g_rows[slot] = row0 + row;
        }
        float Z = 0.f;
        #pragma unroll
        for (int c = 0; c < KEXP; c++) Z += expf(lrow[c] + s_bias[c] - m1);
        float p1 = 1.0f / Z;
        float p2 = expf(m2 - m1) / Z;
        float denom = p1 + p2 + 1e-9f;
        float q1 = p1 / denom, q2 = p2 / denom;
        float ent = -(q1 * logf(fmaxf(q1, 1e-12f)) + q2 * logf(fmaxf(q2, 1e-12f)));
        s_i1[row] = i1; s_i2[row] = i2; s_q1[row] = q1; s_q2[row] = q2;
        out_e[row0 + row] = ent;
    }
    __syncthreads();

    // coalesced sweep: top2_probs + logits (+bias), 128 rows x 16 float4
    #pragma unroll
    for (int i = 0; i < 8; i++) {
        int idx = tid + 256 * i;        // 0..2047
        int row = idx >> 4;
        int col = (idx & 15) * 4;
        int i1 = s_i1[row], i2 = s_i2[row];
        float q1 = s_q1[row], q2 = s_q2[row];
        float4 pv;
        pv.x = (col + 0 == i1) ? q1 : ((col + 0 == i2) ? q2 : 0.f);
        pv.y = (col + 1 == i1) ? q1 : ((col + 1 == i2) ? q2 : 0.f);
        pv.z = (col + 2 == i1) ? q1 : ((col + 2 == i2) ? q2 : 0.f);
        pv.w = (col + 3 == i1) ? q1 : ((col + 3 == i2) ? q2 : 0.f);
        float4 lv;
        lv.x = ls[row * LS_STRIDE + col + 0] + s_bias[col + 0];
        lv.y = ls[row * LS_STRIDE + col + 1] + s_bias[col + 1];
        lv.z = ls[row * LS_STRIDE + col + 2] + s_bias[col + 2];
        lv.w = ls[row * LS_STRIDE + col + 3] + s_bias[col + 3];
        size_t gaddr = (size_t)(row0 + row) * KEXP + col;
        *(float4*)&out_p[gaddr] = pv;
        *(float4*)&out_l[gaddr] = lv;
    }
}

// exact-fp32 repair for near-tie rows: recompute logits, rewrite outputs
__global__ void __launch_bounds__(256, 4)
fix_kernel(const float* __restrict__ x, const float* __restrict__ W,
           const float* __restrict__ b, float* __restrict__ out) {
    __shared__ float sx[DDIM];
    __shared__ float sl[KEXP];
    const int tid = threadIdx.x;
    const int e   = tid >> 2;        // expert 0..63
    const int p   = tid & 3;         // quarter of D
    const int n   = min(g_cnt, MAXFIX);

    float* out_p = out;
    float* out_e = out + (size_t)NTOK * KEXP;
    float* out_l = out_e + NTOK;

    for (int i = blockIdx.x; i < n; i += gridDim.x) {
        const int row = g_rows[i];
        for (int j = tid; j < DDIM; j += 256)
            sx[j] = x[(size_t)row * DDIM + j];
        __syncthreads();

        // 4 threads per expert, interleaved stride-4 partials (coalesced W reads)
        float s = 0.f;
        const float* wr = W + (size_t)e * DDIM + p;
        #pragma unroll 8
        for (int j = 0; j < DDIM / 4; j++)
            s = fmaf(sx[p + 4 * j], wr[4 * j], s);
        s += __shfl_xor_sync(0xFFFFFFFFu, s, 1);
        s += __shfl_xor_sync(0xFFFFFFFFu, s, 2);
        if (p == 0) sl[e] = s + b[e];
        __syncthreads();

        if (tid < KEXP) {
            // redundant per-thread scan (broadcast smem reads)
            float m1 = -1e30f, m2 = -1e30f;
            int i1 = 0, i2 = 0;
            #pragma unroll
            for (int c = 0; c < KEXP; c++) {
                float v = sl[c];
                if (v > m1)      { m2 = m1; i2 = i1; m1 = v; i1 = c; }
                else if (v > m2) { m2 = v;  i2 = c; }
            }
            float Z = 0.f;
            #pragma unroll
            for (int c = 0; c < KEXP; c++) Z += expf(sl[c] - m1);
            float p1 = 1.0f / Z;
            float p2 = expf(m2 - m1) / Z;
            float denom = p1 + p2 + 1e-9f;
            float q1 = p1 / denom, q2 = p2 / denom;
            size_t gr = (size_t)row * KEXP;
            out_l[gr + tid] = sl[tid];
            out_p[gr + tid] = (tid == i1) ? q1 : ((tid == i2) ? q2 : 0.f);
            if (tid == 0)
                out_e[row] = -(q1 * logf(fmaxf(q1, 1e-12f)) +
                               q2 * logf(fmaxf(q2, 1e-12f)));
        }
        __syncthreads();
    }
}

extern "C" void kernel_launch(void* const* d_in, const int* in_sizes, int n_in,
                              void* d_out, int out_size) {
    const float* x = (const float*)d_in[0];
    const float* W = (const float*)d_in[1];
    const float* b = (const float*)d_in[2];
    cudaFuncSetAttribute(top2gate_tc, cudaFuncAttributeMaxDynamicSharedMemorySize, SMEM_TOTAL);
    wprep_kernel<<<1024, 256>>>(W);
    top2gate_tc<<<NTOK / BM, 256, SMEM_TOTAL>>>(x, b, (float*)d_out);
    fix_kernel<<<148, 256>>>(x, W, b, (float*)d_out);
}

// round 5
// speedup vs baseline: 1.7993x; 1.2668x over previous
#include <cuda_runtime.h>
#include <cstdint>

#define NTOK 65536
#define DDIM 2048
#define KEXP 64
#define BM   128
#define KC   32
#define NCHUNK (DDIM / KC)          // 64
#define ASTRIDE 36                  // fp32 words per A row (32 + 4 pad)
#define ABUF_BYTES (BM * ASTRIDE * 4)        // 18432
#define SB_OFF     (2 * ABUF_BYTES)          // 36864
#define BBUF_BYTES (2 * 1024 * 4)            // [plane][2 k16][8 n8][64 words] = 8192
#define SMEM_TOTAL (SB_OFF + 2 * BBUF_BYTES) // 53248
#define LS_STRIDE 68
#define TIE_TAU 2e-3f
#define MAXFIX 8192

// W pre-split into bf16 hi/lo planes, FRAGMENT-MAJOR for m16n8k16 B operand:
// word index = ((p*128 + kb)*8 + nb)*64 + lane*2 + reg
//   halves (lo,hi of word) = plane_p of W[n][k0], W[n][k0+1]
//   n = nb*8 + (lane>>2), k0 = kb*16 + (lane&3)*2 + reg*8
__device__ uint32_t g_Wf[2 * 128 * 8 * 64];
__device__ int g_cnt;
__device__ int g_rows[MAXFIX];

#define CVT_BF16X2(res, f_lo, f_hi) \
    asm("cvt.rn.bf16x2.f32 %0, %1, %2;" : "=r"(res) : "f"(f_hi), "f"(f_lo))

__global__ void wprep_kernel(const float* __restrict__ W) {
    int i = blockIdx.x * 256 + threadIdx.x;          // 0 .. 131071
    if (i == 0) g_cnt = 0;                           // reset flag list every launch
    int reg  = i & 1;
    int lane = (i >> 1) & 31;
    int nb   = (i >> 6) & 7;
    int kb   = (i >> 9) & 127;
    int p    = (i >> 16) & 1;
    int n  = nb * 8 + (lane >> 2);
    int k0 = kb * 16 + (lane & 3) * 2 + reg * 8;
    float v0 = W[n * DDIM + k0];
    float v1 = W[n * DDIM + k0 + 1];
    uint32_t hi;
    CVT_BF16X2(hi, v0, v1);
    if (p == 0) {
        g_Wf[i] = hi;
    } else {
        float h0 = __uint_as_float(hi << 16);
        float h1 = __uint_as_float(hi & 0xffff0000u);
        uint32_t lo;
        CVT_BF16X2(lo, v0 - h0, v1 - h1);
        g_Wf[i] = lo;
    }
}

#define CP16(dst_u32, src_ptr) \
    asm volatile("cp.async.cg.shared.global [%0], [%1], 16;" :: "r"(dst_u32), "l"(src_ptr))
#define CP_COMMIT() asm volatile("cp.async.commit_group;" ::: "memory")

#define MMA_BF16(c, a, b2) \
    asm volatile("mma.sync.aligned.m16n8k16.row.col.f32.bf16.bf16.f32 " \
                 "{%0,%1,%2,%3}, {%4,%5,%6,%7}, {%8,%9}, {%0,%1,%2,%3};" \
                 : "+f"((c)[0]), "+f"((c)[1]), "+f"((c)[2]), "+f"((c)[3]) \
                 : "r"((a)[0]), "r"((a)[1]), "r"((a)[2]), "r"((a)[3]), \
                   "r"((b2)[0]), "r"((b2)[1]))

// split fp32 pair -> packed bf16x2 hi + lo (2-term, residual exact)
__device__ __forceinline__ void split2(float a0, float a1, uint32_t& hi, uint32_t& lo) {
    CVT_BF16X2(hi, a0, a1);
    float h0 = __uint_as_float(hi << 16);
    float h1 = __uint_as_float(hi & 0xffff0000u);
    CVT_BF16X2(lo, a0 - h0, a1 - h1);
}

__global__ __launch_bounds__(256, 2)
void top2gate_tc(const float* __restrict__ x,
                 const float* __restrict__ b,
                 float* __restrict__ out) {
    extern __shared__ char smem[];
    uint32_t sb;
    asm("{ .reg .u64 t; cvta.to.shared.u64 t, %1; cvt.u32.u64 %0, t; }"
        : "=r"(sb) : "l"((const void*)smem));

    __shared__ float s_bias[KEXP];
    __shared__ int   s_i1[BM], s_i2[BM];
    __shared__ float s_q1[BM], s_q2[BM];

    const int tid  = threadIdx.x;
    const int lane = tid & 31;
    const int wid  = tid >> 5;
    const int g    = lane >> 2;       // groupID 0..7
    const int tg   = lane & 3;        // tid-in-group
    const int m0   = (wid >> 1) * 32; // warp M-tile base
    const int nbb  = (wid & 1) * 4;   // warp n8-block base
    const int row0 = blockIdx.x * BM;

    if (tid < KEXP) s_bias[tid] = b[tid];

    float acc[2][4][4];
    #pragma unroll
    for (int i = 0; i < 2; i++)
        #pragma unroll
        for (int j = 0; j < 4; j++)
            #pragma unroll
            for (int c = 0; c < 4; c++) acc[i][j][c] = 0.f;

    // ---- async chunk copy: A (raw fp32 x rows) + B (pre-split fragment words) ----
    auto issue_chunk = [&](int t) {
        const int buf = t & 1;
        const float* xs = x + (size_t)row0 * DDIM + t * KC;
        uint32_t da = sb + buf * ABUF_BYTES;
        #pragma unroll
        for (int q = 0; q < 4; q++) {
            int idx = tid + 256 * q;          // 0..1023
            int r   = idx >> 3;               // row 0..127
            int seg = idx & 7;                // 16B segment
            CP16(da + (uint32_t)(r * ASTRIDE + seg * 4) * 4,
                 xs + (size_t)r * DDIM + seg * 4);
        }
        uint32_t db = sb + SB_OFF + buf * BBUF_BYTES;
        #pragma unroll
        for (int q = 0; q < 2; q++) {
            int idx = tid + 256 * q;          // 0..511
            int wo  = idx * 4;                // word offset 0..2047
            int pl  = wo >> 10;
            int rem = wo & 1023;
            CP16(db + (uint32_t)wo * 4,
                 (const void*)(g_Wf + pl * 65536 + t * 1024 + rem));
        }
        CP_COMMIT();
    };

    issue_chunk(0);

    for (int t = 0; t < NCHUNK; t++) {
        if (t + 1 < NCHUNK) {
            issue_chunk(t + 1);
            asm volatile("cp.async.wait_group 1;" ::: "memory");
        } else {
            asm volatile("cp.async.wait_group 0;" ::: "memory");
        }
        __syncthreads();

        const int buf = t & 1;
        const float* A = (const float*)(smem + buf * ABUF_BYTES);
        const uint32_t dbB = sb + SB_OFF + buf * BBUF_BYTES;

        #pragma unroll
        for (int ks = 0; ks < 2; ks++) {
            // A fragments: raw fp32 pairs -> packed bf16x2 hi/lo
            uint32_t ah[2][4], al[2][4];
            const int c0 = ks * 16 + tg * 2;
            #pragma unroll
            for (int i = 0; i < 2; i++) {
                const int rb = m0 + 16 * i + g;
                float2 p0 = *(const float2*)&A[rb * ASTRIDE + c0];
                float2 p1 = *(const float2*)&A[(rb + 8) * ASTRIDE + c0];
                float2 p2 = *(const float2*)&A[rb * ASTRIDE + c0 + 8];
                float2 p3 = *(const float2*)&A[(rb + 8) * ASTRIDE + c0 + 8];
                split2(p0.x, p0.y, ah[i][0], al[i][0]);
                split2(p1.x, p1.y, ah[i][1], al[i][1]);
                split2(p2.x, p2.y, ah[i][2], al[i][2]);
                split2(p3.x, p3.y, ah[i][3], al[i][3]);
            }
            // B fragments (LDS.64 each): [pl][ks][nb][64 words]
            uint32_t bh[4][2], bl[4][2];
            #pragma unroll
            for (int jn = 0; jn < 4; jn++) {
                uint32_t ah_ = dbB + (uint32_t)((0 * 1024 + ks * 512 + (nbb + jn) * 64 + lane * 2) * 4);
                uint32_t al_ = dbB + (uint32_t)((1 * 1024 + ks * 512 + (nbb + jn) * 64 + lane * 2) * 4);
                asm volatile("ld.shared.v2.b32 {%0,%1}, [%2];"
                             : "=r"(bh[jn][0]), "=r"(bh[jn][1]) : "r"(ah_));
                asm volatile("ld.shared.v2.b32 {%0,%1}, [%2];"
                             : "=r"(bl[jn][0]), "=r"(bl[jn][1]) : "r"(al_));
            }
            // 3 split-products into one fp32 accumulator
            #pragma unroll
            for (int i = 0; i < 2; i++)
                #pragma unroll
                for (int jn = 0; jn < 4; jn++) {
                    MMA_BF16(acc[i][jn], ah[i], bh[jn]);
                    MMA_BF16(acc[i][jn], ah[i], bl[jn]);
                    MMA_BF16(acc[i][jn], al[i], bh[jn]);
                }
        }
        __syncthreads();
    }

    // ---- epilogue: park logits (no bias yet) in smem, reusing A buffers ----
    float* ls = (float*)smem;   // [BM][LS_STRIDE]
    #pragma unroll
    for (int i = 0; i < 2; i++)
        #pragma unroll
        for (int jn = 0; jn < 4; jn++) {
            int r = m0 + 16 * i + g;
            int c = nbb * 8 + jn * 8 + 2 * tg;
            *(float2*)&ls[r * LS_STRIDE + c]       = make_float2(acc[i][jn][0], acc[i][jn][1]);
            *(float2*)&ls[(r + 8) * LS_STRIDE + c] = make_float2(acc[i][jn][2], acc[i][jn][3]);
        }
    __syncthreads();

    float* out_p = out;
    float* out_e = out + (size_t)NTOK * KEXP;
    float* out_l = out_e + NTOK;

    if (tid < BM) {
        const int row = tid;
        const float* lrow = &ls[row * LS_STRIDE];
        float m1 = -1e30f, m2 = -1e30f, m3 = -1e30f;
        int i1 = 0, i2 = 0;
        #pragma unroll
        for (int c = 0; c < KEXP; c++) {
            float v = lrow[c] + s_bias[c];
            if (v > m1)      { m3 = m2; m2 = m1; i2 = i1; m1 = v; i1 = c; }
            else if (v > m2) { m3 = m2; m2 = v;  i2 = c; }
            else if (v > m3) { m3 = v; }
        }
        // near-tie at the top-2/top-3 boundary -> flag for exact fp32 repair
        if (m2 - m3 < TIE_TAU) {
            int slot = atomicAdd(&g_cnt, 1);
            if (slot < MAXFIX) g_rows[slot] = row0 + row;
        }
        float Z = 0.f;
        #pragma unroll
        for (int c = 0; c < KEXP; c++) Z += expf(lrow[c] + s_bias[c] - m1);
        float p1 = 1.0f / Z;
        float p2 = expf(m2 - m1) / Z;
        float denom = p1 + p2 + 1e-9f;
        float q1 = p1 / denom, q2 = p2 / denom;
        float ent = -(q1 * logf(fmaxf(q1, 1e-12f)) + q2 * logf(fmaxf(q2, 1e-12f)));
        s_i1[row] = i1; s_i2[row] = i2; s_q1[row] = q1; s_q2[row] = q2;
        out_e[row0 + row] = ent;
    }
    __syncthreads();

    // coalesced sweep: top2_probs + logits (+bias), 128 rows x 16 float4
    #pragma unroll
    for (int i = 0; i < 8; i++) {
        int idx = tid + 256 * i;        // 0..2047
        int row = idx >> 4;
        int col = (idx & 15) * 4;
        int i1 = s_i1[row], i2 = s_i2[row];
        float q1 = s_q1[row], q2 = s_q2[row];
        float4 pv;
        pv.x = (col + 0 == i1) ? q1 : ((col + 0 == i2) ? q2 : 0.f);
        pv.y = (col + 1 == i1) ? q1 : ((col + 1 == i2) ? q2 : 0.f);
        pv.z = (col + 2 == i1) ? q1 : ((col + 2 == i2) ? q2 : 0.f);
        pv.w = (col + 3 == i1) ? q1 : ((col + 3 == i2) ? q2 : 0.f);
        float4 lv;
        lv.x = ls[row * LS_STRIDE + col + 0] + s_bias[col + 0];
        lv.y = ls[row * LS_STRIDE + col + 1] + s_bias[col + 1];
        lv.z = ls[row * LS_STRIDE + col + 2] + s_bias[col + 2];
        lv.w = ls[row * LS_STRIDE + col + 3] + s_bias[col + 3];
        size_t gaddr = (size_t)(row0 + row) * KEXP + col;
        *(float4*)&out_p[gaddr] = pv;
        *(float4*)&out_l[gaddr] = lv;
    }
}

// exact-fp32 repair for near-tie rows: recompute logits, rewrite outputs
__global__ void __launch_bounds__(256, 4)
fix_kernel(const float* __restrict__ x, const float* __restrict__ W,
           const float* __restrict__ b, float* __restrict__ out) {
    __shared__ float sx[DDIM];
    __shared__ float sl[KEXP];
    const int tid = threadIdx.x;
    const int e   = tid >> 2;        // expert 0..63
    const int p   = tid & 3;         // quarter of D
    const int n   = min(g_cnt, MAXFIX);

    float* out_p = out;
    float* out_e = out + (size_t)NTOK * KEXP;
    float* out_l = out_e + NTOK;

    for (int i = blockIdx.x; i < n; i += gridDim.x) {
        const int row = g_rows[i];
        for (int j = tid; j < DDIM; j += 256)
            sx[j] = x[(size_t)row * DDIM + j];
        __syncthreads();

        float s = 0.f;
        const float* wr = W + (size_t)e * DDIM + p;
        #pragma unroll 8
        for (int j = 0; j < DDIM / 4; j++)
            s = fmaf(sx[p + 4 * j], wr[4 * j], s);
        s += __shfl_xor_sync(0xFFFFFFFFu, s, 1);
        s += __shfl_xor_sync(0xFFFFFFFFu, s, 2);
        if (p == 0) sl[e] = s + b[e];
        __syncthreads();

        if (tid < KEXP) {
            float m1 = -1e30f, m2 = -1e30f;
            int i1 = 0, i2 = 0;
            #pragma unroll
            for (int c = 0; c < KEXP; c++) {
                float v = sl[c];
                if (v > m1)      { m2 = m1; i2 = i1; m1 = v; i1 = c; }
                else if (v > m2) { m2 = v;  i2 = c; }
            }
            float Z = 0.f;
            #pragma unroll
            for (int c = 0; c < KEXP; c++) Z += expf(sl[c] - m1);
            float p1 = 1.0f / Z;
            float p2 = expf(m2 - m1) / Z;
            float denom = p1 + p2 + 1e-9f;
            float q1 = p1 / denom, q2 = p2 / denom;
            size_t gr = (size_t)row * KEXP;
            out_l[gr + tid] = sl[tid];
            out_p[gr + tid] = (tid == i1) ? q1 : ((tid == i2) ? q2 : 0.f);
            if (tid == 0)
                out_e[row] = -(q1 * logf(fmaxf(q1, 1e-12f)) +
                               q2 * logf(fmaxf(q2, 1e-12f)));
        }
        __syncthreads();
    }
}

extern "C" void kernel_launch(void* const* d_in, const int* in_sizes, int n_in,
                              void* d_out, int out_size) {
    const float* x = (const float*)d_in[0];
    const float* W = (const float*)d_in[1];
    const float* b = (const float*)d_in[2];
    cudaFuncSetAttribute(top2gate_tc, cudaFuncAttributeMaxDynamicSharedMemorySize, SMEM_TOTAL);
    wprep_kernel<<<512, 256>>>(W);
    top2gate_tc<<<NTOK / BM, 256, SMEM_TOTAL>>>(x, b, (float*)d_out);
    fix_kernel<<<148, 256>>>(x, W, b, (float*)d_out);
}